// round 13
// baseline (speedup 1.0000x reference)
#include <cuda_runtime.h>
#include <stdint.h>
#include <math.h>

#define SS 4096
#define BB 64
#define HH 512
#define SPL 16
#define CH (SS / SPL)   // 256 rows per (b, split)
#define KS 32           // split-K slices for final GEMM
#define KSL 32          // K per slice (2H / KS)
#define NOT 16          // o-tiles in k3b
#define CEXP 32.0f      // fixed softmax shift (cancels exactly in acc/l)

// Scratch (device globals — no allocation allowed; zero-initialized)
__device__ float g_u[BB * HH];               // u[b,j] = sum_i W_a[i,j] h_t[b,i]
__device__ float g_ct[BB * HH];              // c_t
__device__ float g_pl[BB * SPL];             // partial sum-exp
__device__ float g_pacc[BB * SPL * HH];      // partial weighted accumulators
__device__ float g_opart[KS * HH * BB];      // [ks][o][b] GEMM partials (4 MB)
__device__ int   g_cnt_b[BB];                // last-block counters (self-reset)
__device__ int   g_cnt_o[NOT];               // last-block counters (self-reset)

// ---------------------------------------------------------------------------
// K1: u[b,j] = sum_i W_a[i,j] * h_t[b,i].  W_a read EXACTLY ONCE total.
// ---------------------------------------------------------------------------
__global__ void __launch_bounds__(256) k1_proj(const float* __restrict__ W_a,
                                               const float* __restrict__ h_t) {
    __shared__ float h_sh[64][65];
    __shared__ float W_sh[64][8];
    __shared__ float u_sh[8][65];
    const int t = threadIdx.x;
    const int jl = t >> 5, lane = t & 31;
    const int j0 = blockIdx.x * 8;

    float acc0 = 0.f, acc1 = 0.f;
    for (int c = 0; c < 8; c++) {
        const int ibase = c * 64;
        for (int idx = t; idx < 64 * 64; idx += 256) {
            const int bb = idx >> 6, il = idx & 63;
            h_sh[il][bb] = h_t[bb * HH + ibase + il];
        }
        for (int idx = t; idx < 64 * 8; idx += 256) {
            const int il = idx >> 3, jj = idx & 7;
            W_sh[il][jj] = W_a[(ibase + il) * HH + j0 + jj];
        }
        __syncthreads();
#pragma unroll 16
        for (int il = 0; il < 64; il++) {
            const float wv = W_sh[il][jl];
            acc0 += wv * h_sh[il][lane];
            acc1 += wv * h_sh[il][lane + 32];
        }
        __syncthreads();
    }
    u_sh[jl][lane]      = acc0;
    u_sh[jl][lane + 32] = acc1;
    __syncthreads();
    for (int idx = t; idx < 512; idx += 256) {
        const int bb = idx >> 3, jj = idx & 7;
        g_u[bb * HH + j0 + jj] = u_sh[jj][bb];
    }
}

// ---------------------------------------------------------------------------
// K2: single streaming pass, fixed-offset softmax, 4 rows/warp/iter (MLP=16).
// grid = (SPL, B) = 1024 CTAs, block = 256 (8 warps). [R9 body — champion]
// FUSED: last CTA per b combines the SPL partials into c_t (last-block pattern).
// ---------------------------------------------------------------------------
__global__ void __launch_bounds__(256) k2_flash(const float* __restrict__ hs,
                                                const int* __restrict__ mask) {
    const int split = blockIdx.x;
    const int b     = blockIdx.y;
    const int warp  = threadIdx.x >> 5;
    const int lane  = threadIdx.x & 31;

    float4 u4[4];
    const float4* up = reinterpret_cast<const float4*>(g_u + b * HH);
#pragma unroll
    for (int k = 0; k < 4; k++) u4[k] = up[lane + 32 * k];

    float l = 0.f;
    float4 acc[4];
#pragma unroll
    for (int k = 0; k < 4; k++) acc[k] = make_float4(0.f, 0.f, 0.f, 0.f);

    const int base = split * CH + warp * 32;
    const float4* hs4 = reinterpret_cast<const float4*>(hs);

    for (int it = 0; it < 8; it++) {
        const int s = base + it * 4;
        float4 x[4][4];
        int mk[4];
#pragma unroll
        for (int r = 0; r < 4; r++) {
            const size_t rr = ((size_t)(s + r) * BB + b) * (HH / 4);
#pragma unroll
            for (int k = 0; k < 4; k++)
                x[r][k] = __ldcs(&hs4[rr + lane + 32 * k]);
            mk[r] = mask[b * SS + s + r];
        }

        float d[4];
#pragma unroll
        for (int r = 0; r < 4; r++) {
            float dd = 0.f;
#pragma unroll
            for (int k = 0; k < 4; k++)
                dd += x[r][k].x * u4[k].x + x[r][k].y * u4[k].y +
                      x[r][k].z * u4[k].z + x[r][k].w * u4[k].w;
            d[r] = dd;
        }
#pragma unroll
        for (int off = 16; off; off >>= 1) {
#pragma unroll
            for (int r = 0; r < 4; r++)
                d[r] += __shfl_xor_sync(0xffffffffu, d[r], off);
        }
        float p[4];
#pragma unroll
        for (int r = 0; r < 4; r++) {
            float pp = __expf(d[r] - CEXP);
            p[r] = mk[r] ? pp : 0.f;
        }
        l += (p[0] + p[1]) + (p[2] + p[3]);
#pragma unroll
        for (int k = 0; k < 4; k++) {
            acc[k].x += p[0] * x[0][k].x + p[1] * x[1][k].x +
                        p[2] * x[2][k].x + p[3] * x[3][k].x;
            acc[k].y += p[0] * x[0][k].y + p[1] * x[1][k].y +
                        p[2] * x[2][k].y + p[3] * x[3][k].y;
            acc[k].z += p[0] * x[0][k].z + p[1] * x[1][k].z +
                        p[2] * x[2][k].z + p[3] * x[3][k].z;
            acc[k].w += p[0] * x[0][k].w + p[1] * x[1][k].w +
                        p[2] * x[2][k].w + p[3] * x[3][k].w;
        }
    }

    // ---- block combine: plain sums across 8 warps ----
    __shared__ float sl[8];
    __shared__ float sacc[8][HH];   // 16 KB
    if (lane == 0) sl[warp] = l;
    float4* srow = reinterpret_cast<float4*>(sacc[warp]);
#pragma unroll
    for (int k = 0; k < 4; k++) srow[lane + 32 * k] = acc[k];
    __syncthreads();

    const int pidx = b * SPL + split;
    if (threadIdx.x == 0) {
        float L = 0.f;
#pragma unroll
        for (int w = 0; w < 8; w++) L += sl[w];
        g_pl[pidx] = L;
    }
    for (int h = threadIdx.x; h < HH; h += 256) {
        float A = 0.f;
#pragma unroll
        for (int w = 0; w < 8; w++) A += sacc[w][h];
        g_pacc[(size_t)pidx * HH + h] = A;
    }

    // ---- last-block fusion of k3a: last CTA for this b builds c_t[b] ----
    __threadfence();
    __shared__ int isLast;
    if (threadIdx.x == 0) {
        const int old = atomicAdd(&g_cnt_b[b], 1);
        isLast = (old == SPL - 1);
        if (isLast) g_cnt_b[b] = 0;          // self-reset for graph replay
    }
    __syncthreads();
    if (isLast) {
        __threadfence();                      // acquire side
        float L = 0.f;
#pragma unroll
        for (int s = 0; s < SPL; s++) L += g_pl[b * SPL + s];
        const float invL = 1.f / L;
        for (int h = threadIdx.x; h < HH; h += 256) {
            float A = 0.f;
#pragma unroll
            for (int s = 0; s < SPL; s++)
                A += g_pacc[(size_t)(b * SPL + s) * HH + h];
            g_ct[b * HH + h] = A * invL;
        }
    }
}

// ---------------------------------------------------------------------------
// K3b: split-K GEMM partials + FUSED finisher (k3c) via last-block pattern.
// grid = (16 o-tiles of 32, 32 k-slices) = 512 CTAs, block = 256.
// ---------------------------------------------------------------------------
__global__ void __launch_bounds__(256) k3b_gemm(const float* __restrict__ h_t,
                                                const float* __restrict__ W_r,
                                                const float* __restrict__ b_r,
                                                float* __restrict__ out) {
    __shared__ float cat_sh[64][36];
    __shared__ float W_sh[32][36];
    const int t = threadIdx.x;
    const int otile = blockIdx.x;
    const int ks    = blockIdx.y;
    const int kbase = ks * KSL;

    const float* src = (kbase < HH) ? (g_ct + kbase) : (h_t + (kbase - HH));
    for (int i = t; i < 64 * 8; i += 256) {
        const int bb = i >> 3, k4 = i & 7;
        const float4 v = *reinterpret_cast<const float4*>(src + bb * HH + k4 * 4);
        *reinterpret_cast<float4*>(&cat_sh[bb][k4 * 4]) = v;
    }
    if (t < 32 * 8) {
        const int oo = t >> 3, k4 = t & 7;
        const float4 v = *reinterpret_cast<const float4*>(
            W_r + (size_t)(otile * 32 + oo) * (2 * HH) + kbase + k4 * 4);
        *reinterpret_cast<float4*>(&W_sh[oo][k4 * 4]) = v;
    }
    __syncthreads();

    const int b = t & 63, og = t >> 6;
    float acc[8];
#pragma unroll
    for (int j = 0; j < 8; j++) acc[j] = 0.f;

#pragma unroll
    for (int kk = 0; kk < 8; kk++) {
        const float4 c4 = *reinterpret_cast<const float4*>(&cat_sh[b][kk * 4]);
#pragma unroll
        for (int j = 0; j < 8; j++) {
            const float4 w4 =
                *reinterpret_cast<const float4*>(&W_sh[og * 8 + j][kk * 4]);
            acc[j] += c4.x * w4.x + c4.y * w4.y + c4.z * w4.z + c4.w * w4.w;
        }
    }
#pragma unroll
    for (int j = 0; j < 8; j++) {
        const int o = otile * 32 + og * 8 + j;
        g_opart[(size_t)ks * HH * BB + o * BB + b] = acc[j];
    }

    // ---- last-block fusion of k3c: last ks-CTA per otile writes out ----
    __threadfence();
    __shared__ int isLast;
    if (t == 0) {
        const int old = atomicAdd(&g_cnt_o[otile], 1);
        isLast = (old == KS - 1);
        if (isLast) g_cnt_o[otile] = 0;       // self-reset for graph replay
    }
    __syncthreads();
    if (isLast) {
        __threadfence();                      // acquire side
        for (int i = t; i < 32 * 64; i += 256) {
            const int oo = i >> 6, bb = i & 63;
            const int o = otile * 32 + oo;
            float s = 0.f;
#pragma unroll
            for (int k2 = 0; k2 < KS; k2++)
                s += g_opart[(size_t)k2 * HH * BB + o * BB + bb];
            out[bb * HH + o] = tanhf(s + b_r[o]);
        }
    }
}

// ---------------------------------------------------------------------------
extern "C" void kernel_launch(void* const* d_in, const int* in_sizes, int n_in,
                              void* d_out, int out_size) {
    const float* hs   = (const float*)d_in[0];   // [S,B,H]
    const float* h_t  = (const float*)d_in[1];   // [B,H]
    const int*   mask = (const int*)  d_in[2];   // [B,S]
    const float* W_a  = (const float*)d_in[3];   // [H,H]
    // d_in[4] = b_a : cancels in softmax (per-b constant)
    const float* W_r  = (const float*)d_in[5];   // [H,2H]
    const float* b_r  = (const float*)d_in[6];   // [H]
    float* out = (float*)d_out;                  // [B,H]

    k1_proj<<<HH / 8, 256>>>(W_a, h_t);
    k2_flash<<<dim3(SPL, BB), 256>>>(hs, mask);
    k3b_gemm<<<dim3(NOT, KS), 256>>>(h_t, W_r, b_r, out);
}

// round 14
// speedup vs baseline: 1.2243x; 1.2243x over previous
#include <cuda_runtime.h>
#include <stdint.h>
#include <math.h>

#define SS 4096
#define BB 64
#define HH 512
#define SPL 16
#define CH (SS / SPL)   // 256 rows per (b, split)
#define KS 32           // split-K slices for final GEMM
#define KSL 32          // K per slice (2H / KS)
#define CEXP 32.0f      // fixed softmax shift (cancels exactly in acc/l)

// Scratch (device globals — no allocation allowed)
__device__ float g_u[BB * HH];               // u[b,j] = sum_i W_a[i,j] h_t[b,i]
__device__ float g_ct[BB * HH];              // c_t
__device__ float g_pl[BB * SPL];             // partial sum-exp
__device__ float g_pacc[BB * SPL * HH];      // partial weighted accumulators
__device__ float g_opart[KS * HH * BB];      // [ks][o][b] GEMM partials (4 MB)

// ---------------------------------------------------------------------------
// K1 (rewritten for parallelism): u[b,j] = sum_i W_a[i,j] * h_t[b,i].
// grid = (4 j-tiles, 64 b) = 256 CTAs, block = 256 (8 warps).
// Warp w sums i in [w*64, w*64+64); lane covers one float4 of the j-tile.
// W_a rows read as coalesced 512B float4 bursts; L2-resident after first b.
// ---------------------------------------------------------------------------
__global__ void __launch_bounds__(256) k1_proj(const float* __restrict__ W_a,
                                               const float* __restrict__ h_t) {
    const int jt = blockIdx.x;          // 0..3 -> float4 cols jt*32..jt*32+31
    const int b  = blockIdx.y;
    const int t  = threadIdx.x;
    const int warp = t >> 5, lane = t & 31;

    __shared__ float  h_sh[HH];
    __shared__ float4 sacc[8][32];

    for (int i = t; i < HH; i += 256) h_sh[i] = h_t[b * HH + i];
    __syncthreads();

    const float4* W4 = reinterpret_cast<const float4*>(W_a);  // [512][128]
    float4 a = make_float4(0.f, 0.f, 0.f, 0.f);
    const int i0 = warp * 64;
#pragma unroll 8
    for (int ii = 0; ii < 64; ii++) {
        const int i = i0 + ii;
        const float4 w = W4[(size_t)i * 128 + jt * 32 + lane];
        const float  h = h_sh[i];                // broadcast, conflict-free
        a.x += w.x * h; a.y += w.y * h; a.z += w.z * h; a.w += w.w * h;
    }
    sacc[warp][lane] = a;
    __syncthreads();

    if (t < 32) {
        float4 s = sacc[0][t];
#pragma unroll
        for (int w = 1; w < 8; w++) {
            const float4 v = sacc[w][t];
            s.x += v.x; s.y += v.y; s.z += v.z; s.w += v.w;
        }
        reinterpret_cast<float4*>(g_u + b * HH)[jt * 32 + t] = s;
    }
}

// ---------------------------------------------------------------------------
// K2: single streaming pass, fixed-offset softmax, 4 rows/warp/iter (MLP=16).
// grid = (SPL, B) = 1024 CTAs, block = 256 (8 warps). [R9 champion body]
// ---------------------------------------------------------------------------
__global__ void __launch_bounds__(256) k2_flash(const float* __restrict__ hs,
                                                const int* __restrict__ mask) {
    const int split = blockIdx.x;
    const int b     = blockIdx.y;
    const int warp  = threadIdx.x >> 5;
    const int lane  = threadIdx.x & 31;

    float4 u4[4];
    const float4* up = reinterpret_cast<const float4*>(g_u + b * HH);
#pragma unroll
    for (int k = 0; k < 4; k++) u4[k] = up[lane + 32 * k];

    float l = 0.f;
    float4 acc[4];
#pragma unroll
    for (int k = 0; k < 4; k++) acc[k] = make_float4(0.f, 0.f, 0.f, 0.f);

    const int base = split * CH + warp * 32;
    const float4* hs4 = reinterpret_cast<const float4*>(hs);

    for (int it = 0; it < 8; it++) {
        const int s = base + it * 4;
        float4 x[4][4];
        int mk[4];
#pragma unroll
        for (int r = 0; r < 4; r++) {
            const size_t rr = ((size_t)(s + r) * BB + b) * (HH / 4);
#pragma unroll
            for (int k = 0; k < 4; k++)
                x[r][k] = __ldcs(&hs4[rr + lane + 32 * k]);
            mk[r] = mask[b * SS + s + r];
        }

        float d[4];
#pragma unroll
        for (int r = 0; r < 4; r++) {
            float dd = 0.f;
#pragma unroll
            for (int k = 0; k < 4; k++)
                dd += x[r][k].x * u4[k].x + x[r][k].y * u4[k].y +
                      x[r][k].z * u4[k].z + x[r][k].w * u4[k].w;
            d[r] = dd;
        }
#pragma unroll
        for (int off = 16; off; off >>= 1) {
#pragma unroll
            for (int r = 0; r < 4; r++)
                d[r] += __shfl_xor_sync(0xffffffffu, d[r], off);
        }
        float p[4];
#pragma unroll
        for (int r = 0; r < 4; r++) {
            float pp = __expf(d[r] - CEXP);
            p[r] = mk[r] ? pp : 0.f;
        }
        l += (p[0] + p[1]) + (p[2] + p[3]);
#pragma unroll
        for (int k = 0; k < 4; k++) {
            acc[k].x += p[0] * x[0][k].x + p[1] * x[1][k].x +
                        p[2] * x[2][k].x + p[3] * x[3][k].x;
            acc[k].y += p[0] * x[0][k].y + p[1] * x[1][k].y +
                        p[2] * x[2][k].y + p[3] * x[3][k].y;
            acc[k].z += p[0] * x[0][k].z + p[1] * x[1][k].z +
                        p[2] * x[2][k].z + p[3] * x[3][k].z;
            acc[k].w += p[0] * x[0][k].w + p[1] * x[1][k].w +
                        p[2] * x[2][k].w + p[3] * x[3][k].w;
        }
    }

    // ---- block combine: plain sums across 8 warps ----
    __shared__ float sl[8];
    __shared__ float sacc[8][HH];   // 16 KB
    if (lane == 0) sl[warp] = l;
    float4* srow = reinterpret_cast<float4*>(sacc[warp]);
#pragma unroll
    for (int k = 0; k < 4; k++) srow[lane + 32 * k] = acc[k];
    __syncthreads();

    const int pidx = b * SPL + split;
    if (threadIdx.x == 0) {
        float L = 0.f;
#pragma unroll
        for (int w = 0; w < 8; w++) L += sl[w];
        g_pl[pidx] = L;
    }
    for (int h = threadIdx.x; h < HH; h += 256) {
        float A = 0.f;
#pragma unroll
        for (int w = 0; w < 8; w++) A += sacc[w][h];
        g_pacc[(size_t)pidx * HH + h] = A;
    }
}

// ---------------------------------------------------------------------------
// K3a: combine SPL partials -> c_t  (plain sums; shift cancels in A/L)
// ---------------------------------------------------------------------------
__global__ void __launch_bounds__(512) k3a_combine() {
    const int b = blockIdx.x, h = threadIdx.x;
    float L = 0.f, A = 0.f;
#pragma unroll
    for (int s = 0; s < SPL; s++) {
        L += g_pl[b * SPL + s];
        A += g_pacc[(size_t)(b * SPL + s) * HH + h];
    }
    g_ct[b * HH + h] = A / L;
}

// ---------------------------------------------------------------------------
// K3b: split-K GEMM partials (R5 config — measured best):
// grid = (16 o-tiles of 32, 32 k-slices) = 512 CTAs, block = 256.
// ---------------------------------------------------------------------------
__global__ void __launch_bounds__(256) k3b_gemm(const float* __restrict__ h_t,
                                                const float* __restrict__ W_r) {
    __shared__ float cat_sh[64][36];
    __shared__ float W_sh[32][36];
    const int t = threadIdx.x;
    const int otile = blockIdx.x;
    const int ks    = blockIdx.y;
    const int kbase = ks * KSL;

    const float* src = (kbase < HH) ? (g_ct + kbase) : (h_t + (kbase - HH));
    for (int i = t; i < 64 * 8; i += 256) {
        const int bb = i >> 3, k4 = i & 7;
        const float4 v = *reinterpret_cast<const float4*>(src + bb * HH + k4 * 4);
        *reinterpret_cast<float4*>(&cat_sh[bb][k4 * 4]) = v;
    }
    if (t < 32 * 8) {
        const int oo = t >> 3, k4 = t & 7;
        const float4 v = *reinterpret_cast<const float4*>(
            W_r + (size_t)(otile * 32 + oo) * (2 * HH) + kbase + k4 * 4);
        *reinterpret_cast<float4*>(&W_sh[oo][k4 * 4]) = v;
    }
    __syncthreads();

    const int b = t & 63, og = t >> 6;
    float acc[8];
#pragma unroll
    for (int j = 0; j < 8; j++) acc[j] = 0.f;

#pragma unroll
    for (int kk = 0; kk < 8; kk++) {
        const float4 c4 = *reinterpret_cast<const float4*>(&cat_sh[b][kk * 4]);
#pragma unroll
        for (int j = 0; j < 8; j++) {
            const float4 w4 =
                *reinterpret_cast<const float4*>(&W_sh[og * 8 + j][kk * 4]);
            acc[j] += c4.x * w4.x + c4.y * w4.y + c4.z * w4.z + c4.w * w4.w;
        }
    }
#pragma unroll
    for (int j = 0; j < 8; j++) {
        const int o = otile * 32 + og * 8 + j;
        g_opart[(size_t)ks * HH * BB + o * BB + b] = acc[j];
    }
}

// ---------------------------------------------------------------------------
// K3c: out[b,o] = tanh(b_r[o] + sum_ks opart[ks][o][b]); smem transpose write.
// ---------------------------------------------------------------------------
__global__ void __launch_bounds__(512) k3c_fin(const float* __restrict__ b_r,
                                               float* __restrict__ out) {
    __shared__ float sh[8][65];
    const int c = blockIdx.x;
    const int t = threadIdx.x;
    const int j = t >> 6, b = t & 63;
    const int o = c * 8 + j;
    float s = 0.f;
#pragma unroll
    for (int ks = 0; ks < KS; ks++)
        s += g_opart[(size_t)ks * HH * BB + o * BB + b];
    sh[j][b] = tanhf(s + b_r[o]);
    __syncthreads();
    const int b2 = t >> 3, j2 = t & 7;
    out[b2 * HH + c * 8 + j2] = sh[j2][b2];
}

// ---------------------------------------------------------------------------
extern "C" void kernel_launch(void* const* d_in, const int* in_sizes, int n_in,
                              void* d_out, int out_size) {
    const float* hs   = (const float*)d_in[0];   // [S,B,H]
    const float* h_t  = (const float*)d_in[1];   // [B,H]
    const int*   mask = (const int*)  d_in[2];   // [B,S]
    const float* W_a  = (const float*)d_in[3];   // [H,H]
    // d_in[4] = b_a : cancels in softmax (per-b constant)
    const float* W_r  = (const float*)d_in[5];   // [H,2H]
    const float* b_r  = (const float*)d_in[6];   // [H]
    float* out = (float*)d_out;                  // [B,H]

    k1_proj<<<dim3(4, BB), 256>>>(W_a, h_t);
    k2_flash<<<dim3(SPL, BB), 256>>>(hs, mask);
    k3a_combine<<<BB, 512>>>();
    k3b_gemm<<<dim3(16, KS), 256>>>(h_t, W_r);
    k3c_fin<<<BB, 512>>>(b_r, out);
}